// round 5
// baseline (speedup 1.0000x reference)
#include <cuda_runtime.h>
#include <cstdint>

#define THREADS 128
#define NB 128
#define XS 68          // x smem row stride (floats); 272B = 17 granules -> conflict-free LDSM
#define WS 68

__device__ __forceinline__ uint32_t smem_u32(const void* p) {
    uint32_t a;
    asm("{ .reg .u64 t; cvta.to.shared.u64 t, %1; cvt.u32.u64 %0, t; }" : "=r"(a) : "l"(p));
    return a;
}

__device__ __forceinline__ void ldsm_x4(uint32_t* r, uint32_t addr) {
    asm volatile("ldmatrix.sync.aligned.m8n8.x4.shared.b16 {%0,%1,%2,%3}, [%4];"
                 : "=r"(r[0]), "=r"(r[1]), "=r"(r[2]), "=r"(r[3]) : "r"(addr));
}

__device__ __forceinline__ void mma_tf32(float* d, const uint32_t* a, const uint32_t* b) {
    asm volatile("mma.sync.aligned.m16n8k8.row.col.f32.tf32.tf32.f32 "
                 "{%0,%1,%2,%3},{%4,%5,%6,%7},{%8,%9},{%0,%1,%2,%3};"
                 : "+f"(d[0]), "+f"(d[1]), "+f"(d[2]), "+f"(d[3])
                 : "r"(a[0]), "r"(a[1]), "r"(a[2]), "r"(a[3]), "r"(b[0]), "r"(b[1]));
}

// Shapes: x (65536,25,64) f32; weight (4,64,64) f32; out (65536,35,64) f32.
// out[n,m,:] = x[n,m+1,:] @ W[deg(m)]  for m<24;  out[n,24:35,:] = 0.

__global__ __launch_bounds__(THREADS)
void dwl_mma_kernel(const float* __restrict__ x,
                    const float* __restrict__ weight,
                    float* __restrict__ out)
{
    extern __shared__ float smem[];
    float* xs = smem;                   // 128 x 68
    float* wh = smem + NB * XS;         // 64 x 68 (W^T hi)
    float* wl = wh + 64 * WS;           // 64 x 68 (W^T lo)

    const int t    = threadIdx.x;
    const int lane = t & 31;
    const int wid  = t >> 5;
    const long long n0 = (long long)blockIdx.x * NB;

    // --- zero-fill orders 24..34 (11*64 floats per row) ---
    {
        const float4 z = make_float4(0.f, 0.f, 0.f, 0.f);
        #pragma unroll 4
        for (int i = t; i < NB * 176; i += THREADS) {
            int r = i / 176;
            int j = i - r * 176;
            ((float4*)(out + (n0 + r) * 2240 + 1536))[j] = z;
        }
    }

    const uint32_t xs_b = smem_u32(xs);
    const uint32_t wh_b = smem_u32(wh);
    const uint32_t wl_b = smem_u32(wl);
    const uint32_t mhi  = 0xFFFFE000u;      // tf32-significant bits of fp32

    const int cbase = wid * 16;             // this warp's output col base

    // ldmatrix lane-address components
    // A (x tile, row-major m16k8): matrices = (rows 0-7, k0..3),(rows 8-15, k0..3),
    //                                         (rows 0-7, k4..7),(rows 8-15, k4..7)
    const uint32_t a_row  = (uint32_t)(lane & 15);
    const uint32_t a_koff = (uint32_t)(lane >> 4) * 16;   // bytes
    // B (W^T, [n][k]): matrices = (n 0-7, k0..3),(n 0-7, k4..7),(n 8-15, k0..3),(n 8-15, k4..7)
    const int blk = lane >> 3;
    const uint32_t b_n    = (uint32_t)(cbase + ((blk >> 1) << 3) + (lane & 7));
    const uint32_t b_koff = (uint32_t)(blk & 1) * 16;

    uint32_t bh[2][8][2], bl[2][8][2];      // [ntile][kstep][b0/b1]

    for (int deg = 0; deg < 4; deg++) {
        const int l     = deg + 1;
        const int ms    = l * l - 1;        // first m of this degree
        const int mcnt  = 2 * l + 1;

        // --- stage W^T hi/lo in smem (coalesced read, scatter write) ---
        const float* Wg = weight + deg * 4096;
        #pragma unroll 8
        for (int i = t; i < 4096; i += THREADS) {
            int k = i >> 6, d = i & 63;
            float v  = Wg[i];
            float hi = __uint_as_float(__float_as_uint(v) & mhi);
            wh[d * WS + k] = hi;
            wl[d * WS + k] = v - hi;
        }
        __syncthreads();

        // --- load this warp's W fragments into registers (persist over m loop) ---
        #pragma unroll
        for (int ks = 0; ks < 8; ks++) {
            uint32_t r[4];
            ldsm_x4(r, wh_b + b_n * (WS * 4) + b_koff + ks * 32);
            bh[0][ks][0] = r[0]; bh[0][ks][1] = r[1];
            bh[1][ks][0] = r[2]; bh[1][ks][1] = r[3];
            ldsm_x4(r, wl_b + b_n * (WS * 4) + b_koff + ks * 32);
            bl[0][ks][0] = r[0]; bl[0][ks][1] = r[1];
            bl[1][ks][0] = r[2]; bl[1][ks][1] = r[3];
        }

        for (int mi = 0; mi < mcnt; mi++) {
            const int m = ms + mi;
            __syncthreads();   // previous m's LDSM reads of xs complete

            // --- stage x tile (order m+1), coalesced float4 ---
            const float* Xg = x + (n0 * 25 + (m + 1)) * 64;
            #pragma unroll
            for (int j = 0; j < 16; j++) {
                int i  = t + THREADS * j;
                int r  = i >> 4;
                int c4 = (i & 15) << 2;
                float4 v = *(const float4*)(Xg + (long long)r * 1600 + c4);
                *(float4*)(xs + r * XS + c4) = v;
            }
            __syncthreads();

            // --- compute: 8 m16-tiles, K=64 (8 k8 steps), 3-pass tf32 split ---
            #pragma unroll
            for (int mt = 0; mt < 8; mt++) {
                float acc0[4] = {0.f, 0.f, 0.f, 0.f};
                float acc1[4] = {0.f, 0.f, 0.f, 0.f};
                const uint32_t abase = xs_b + (mt * 16 + a_row) * (XS * 4) + a_koff;
                #pragma unroll
                for (int ks = 0; ks < 8; ks++) {
                    uint32_t a[4];
                    ldsm_x4(a, abase + ks * 32);
                    uint32_t ah[4], al[4];
                    #pragma unroll
                    for (int j = 0; j < 4; j++) {
                        ah[j] = a[j] & mhi;
                        float lo = __uint_as_float(a[j]) - __uint_as_float(ah[j]);
                        al[j] = __float_as_uint(lo);
                    }
                    mma_tf32(acc0, ah, bh[0][ks]);
                    mma_tf32(acc0, al, bh[0][ks]);
                    mma_tf32(acc0, ah, bl[0][ks]);
                    mma_tf32(acc1, ah, bh[1][ks]);
                    mma_tf32(acc1, al, bh[1][ks]);
                    mma_tf32(acc1, ah, bl[1][ks]);
                }
                // --- store D fragments (float2, 8B aligned) ---
                const long long row = n0 + mt * 16 + (lane >> 2);
                const int col = m * 64 + cbase + (lane & 3) * 2;
                *(float2*)(out + row * 2240 + col)           = make_float2(acc0[0], acc0[1]);
                *(float2*)(out + (row + 8) * 2240 + col)     = make_float2(acc0[2], acc0[3]);
                *(float2*)(out + row * 2240 + col + 8)       = make_float2(acc1[0], acc1[1]);
                *(float2*)(out + (row + 8) * 2240 + col + 8) = make_float2(acc1[2], acc1[3]);
            }
        }
        __syncthreads();  // all warps done with wh/wl + xs before next degree restages
    }
}

extern "C" void kernel_launch(void* const* d_in, const int* in_sizes, int n_in,
                              void* d_out, int out_size)
{
    const float* x = (const float*)d_in[0];
    const float* w = (const float*)d_in[1];
    if (n_in >= 2 && in_sizes[0] < in_sizes[1]) {
        x = (const float*)d_in[1];
        w = (const float*)d_in[0];
    }
    float* out = (float*)d_out;

    const int smem_sz = (NB * XS + 2 * 64 * WS) * sizeof(float);  // 69632 B
    cudaFuncSetAttribute(dwl_mma_kernel,
                         cudaFuncAttributeMaxDynamicSharedMemorySize, smem_sz);
    dwl_mma_kernel<<<65536 / NB, THREADS, smem_sz>>>(x, w, out);
}

// round 7
// speedup vs baseline: 1.5506x; 1.5506x over previous
#include <cuda_runtime.h>
#include <cstdint>

#define THREADS 128
#define NB 64
#define XS 68                    // smem row stride (floats): 272B, conflict-free LDSM phases
#define BUFF (NB * XS)           // floats per x ring buffer

// W^T hi/lo in per-lane mma-fragment order:
// [deg][cw][nt][ks][h][lane*2+r]  -> 4*4*2*8*2*64 floats = 32768 floats (128KB)
__device__ float w_frag[4 * 4 * 2 * 8 * 2 * 64];

__device__ __forceinline__ uint32_t smem_u32(const void* p) {
    uint32_t a;
    asm("{ .reg .u64 t; cvta.to.shared.u64 t, %1; cvt.u32.u64 %0, t; }" : "=r"(a) : "l"(p));
    return a;
}
__device__ __forceinline__ void ldsm_x4(uint32_t* r, uint32_t addr) {
    asm volatile("ldmatrix.sync.aligned.m8n8.x4.shared.b16 {%0,%1,%2,%3}, [%4];"
                 : "=r"(r[0]), "=r"(r[1]), "=r"(r[2]), "=r"(r[3]) : "r"(addr));
}
__device__ __forceinline__ void mma_tf32(float* d, const uint32_t* a, const uint32_t* b) {
    asm volatile("mma.sync.aligned.m16n8k8.row.col.f32.tf32.tf32.f32 "
                 "{%0,%1,%2,%3},{%4,%5,%6,%7},{%8,%9},{%0,%1,%2,%3};"
                 : "+f"(d[0]), "+f"(d[1]), "+f"(d[2]), "+f"(d[3])
                 : "r"(a[0]), "r"(a[1]), "r"(a[2]), "r"(a[3]), "r"(b[0]), "r"(b[1]));
}
__device__ __forceinline__ void cp16(uint32_t saddr, const void* gaddr) {
    asm volatile("cp.async.cg.shared.global [%0], [%1], 16;" :: "r"(saddr), "l"(gaddr));
}

// ---- prep: W (4,64,64) -> w_frag, tf32 hi/lo split, fragment layout ----
// b0: k = lane&3,  n = lane>>2 ;  b1: k = (lane&3)+4, n = lane>>2  (per 8x8 tile)
// i is a 15-bit index: r(1) lane(5) h(1) ks(3) nt(1) cw(2) deg(2)
__global__ void prep_kernel(const float* __restrict__ weight) {
    int i = blockIdx.x * blockDim.x + threadIdx.x;   // 0..32767
    int r    = i & 1;
    int lane = (i >> 1) & 31;
    int h    = (i >> 6) & 1;
    int ks   = (i >> 7) & 7;
    int nt   = (i >> 10) & 1;
    int cw   = (i >> 11) & 3;
    int deg  = (i >> 13) & 3;
    int n = cw * 16 + nt * 8 + (lane >> 2);
    int k = ks * 8 + (lane & 3) + r * 4;
    float v  = weight[deg * 4096 + k * 64 + n];
    float hi = __uint_as_float(__float_as_uint(v) & 0xFFFFE000u);
    w_frag[i] = (h == 0) ? hi : (v - hi);
}

// ---- main: x (65536,25,64) -> out (65536,35,64) ----
__global__ __launch_bounds__(THREADS, 4)
void dwl_main(const float* __restrict__ x, float* __restrict__ out)
{
    extern __shared__ float xs[];
    const int t    = threadIdx.x;
    const int lane = t & 31;
    const int cw   = t >> 5;                 // col-warp: cols cw*16..cw*16+15
    const long long n0 = (long long)blockIdx.x * NB;

    // zero-fill orders 24..34
    {
        const float4 z = make_float4(0.f, 0.f, 0.f, 0.f);
        for (int i = t; i < NB * 176; i += THREADS) {
            int r = i / 176;
            int j = i - r * 176;
            ((float4*)(out + (n0 + r) * 2240 + 1536))[j] = z;
        }
    }

    const uint32_t xs_b = smem_u32(xs);
    const uint32_t mhi  = 0xFFFFE000u;

    // A-frag ldmatrix addressing (validated in R5)
    const uint32_t a_row  = (uint32_t)(lane & 15);
    const uint32_t a_koff = (uint32_t)(lane >> 4) * 16;

    // stage x tile for order m into ring slot b (64 rows x 16 x 16B chunks)
    auto stage = [&](int m, int b) {
        const char* Xg = (const char*)(x + (n0 * 25 + (m + 1)) * 64);
        uint32_t sb = xs_b + b * (BUFF * 4);
        #pragma unroll
        for (int j = 0; j < 8; j++) {
            int i = t + THREADS * j;
            int r = i >> 4;
            int c = i & 15;
            cp16(sb + (uint32_t)(r * (XS * 4) + c * 16),
                 Xg + (long long)r * 6400 + c * 16);
        }
        asm volatile("cp.async.commit_group;" ::: "memory");
    };

    uint32_t bh[2][8][2], bl[2][8][2];
    auto load_bfrags = [&](int deg) {
        #pragma unroll
        for (int nt = 0; nt < 2; nt++)
            #pragma unroll
            for (int ks = 0; ks < 8; ks++) {
                const float* p = w_frag + ((((deg * 4 + cw) * 2 + nt) * 8 + ks) * 2) * 64
                                 + lane * 2;
                float2 h2 = *(const float2*)p;
                float2 l2 = *(const float2*)(p + 64);
                bh[nt][ks][0] = __float_as_uint(h2.x);
                bh[nt][ks][1] = __float_as_uint(h2.y);
                bl[nt][ks][0] = __float_as_uint(l2.x);
                bl[nt][ks][1] = __float_as_uint(l2.y);
            }
    };

    stage(0, 0);
    load_bfrags(0);
    int deg = 0;

    for (int m = 0; m < 24; m++) {
        if (m < 23) {
            stage(m + 1, (m + 1) % 3);
            asm volatile("cp.async.wait_group 1;" ::: "memory");
        } else {
            asm volatile("cp.async.wait_group 0;" ::: "memory");
        }
        __syncthreads();

        if (m == 3 || m == 8 || m == 15) { deg++; load_bfrags(deg); }

        const uint32_t abase0 = xs_b + (m % 3) * (BUFF * 4) + a_row * (XS * 4) + a_koff;

        #pragma unroll
        for (int mt = 0; mt < 4; mt++) {
            float acc0[4] = {0.f, 0.f, 0.f, 0.f};
            float acc1[4] = {0.f, 0.f, 0.f, 0.f};
            const uint32_t abase = abase0 + (uint32_t)(mt * 16 * XS * 4);
            #pragma unroll
            for (int ks = 0; ks < 8; ks++) {
                uint32_t a[4];
                ldsm_x4(a, abase + ks * 32);
                uint32_t ah[4], al[4];
                #pragma unroll
                for (int j = 0; j < 4; j++) {
                    ah[j] = a[j] & mhi;
                    float lo = __uint_as_float(a[j]) - __uint_as_float(ah[j]);
                    al[j] = __float_as_uint(lo);
                }
                mma_tf32(acc0, ah, bh[0][ks]);
                mma_tf32(acc0, al, bh[0][ks]);
                mma_tf32(acc0, ah, bl[0][ks]);
                mma_tf32(acc1, ah, bh[1][ks]);
                mma_tf32(acc1, al, bh[1][ks]);
                mma_tf32(acc1, ah, bl[1][ks]);
            }
            const long long row = n0 + mt * 16 + (lane >> 2);
            const int col = m * 64 + cw * 16 + (lane & 3) * 2;
            *(float2*)(out + row * 2240 + col)           = make_float2(acc0[0], acc0[1]);
            *(float2*)(out + (row + 8) * 2240 + col)     = make_float2(acc0[2], acc0[3]);
            *(float2*)(out + row * 2240 + col + 8)       = make_float2(acc1[0], acc1[1]);
            *(float2*)(out + (row + 8) * 2240 + col + 8) = make_float2(acc1[2], acc1[3]);
        }
        // no trailing sync: ring depth 3 => slot written in iter m was last
        // read in iter m-2; the barrier in iter m-1 orders reads before writes.
    }
}

extern "C" void kernel_launch(void* const* d_in, const int* in_sizes, int n_in,
                              void* d_out, int out_size)
{
    const float* x = (const float*)d_in[0];
    const float* w = (const float*)d_in[1];
    if (n_in >= 2 && in_sizes[0] < in_sizes[1]) {
        x = (const float*)d_in[1];
        w = (const float*)d_in[0];
    }
    float* out = (float*)d_out;

    prep_kernel<<<32, 1024>>>(w);   // 32768 threads: one per w_frag element

    const int smem_sz = 3 * BUFF * sizeof(float);   // 52224 B
    cudaFuncSetAttribute(dwl_main, cudaFuncAttributeMaxDynamicSharedMemorySize, smem_sz);
    dwl_main<<<65536 / NB, THREADS, smem_sz>>>(x, out);
}

// round 8
// speedup vs baseline: 2.0544x; 1.3249x over previous
#include <cuda_runtime.h>
#include <cstdint>

#define THREADS 128
#define NB 32
#define XS 68                    // smem row stride (floats): 272B, conflict-free LDSM phases
#define BUFF (NB * XS)           // floats per x ring buffer

// W^T (tf32 RN-rounded) in per-lane mma-fragment order:
// [deg][cw][nt][ks][lane*2+r]  -> 4*4*2*8*64 = 16384 floats
__device__ float w_frag[4 * 4 * 2 * 8 * 64];

__device__ __forceinline__ uint32_t smem_u32(const void* p) {
    uint32_t a;
    asm("{ .reg .u64 t; cvta.to.shared.u64 t, %1; cvt.u32.u64 %0, t; }" : "=r"(a) : "l"(p));
    return a;
}
__device__ __forceinline__ void ldsm_x4(uint32_t* r, uint32_t addr) {
    asm volatile("ldmatrix.sync.aligned.m8n8.x4.shared.b16 {%0,%1,%2,%3}, [%4];"
                 : "=r"(r[0]), "=r"(r[1]), "=r"(r[2]), "=r"(r[3]) : "r"(addr));
}
__device__ __forceinline__ void mma_tf32(float* d, const uint32_t* a, const uint32_t* b) {
    asm volatile("mma.sync.aligned.m16n8k8.row.col.f32.tf32.tf32.f32 "
                 "{%0,%1,%2,%3},{%4,%5,%6,%7},{%8,%9},{%0,%1,%2,%3};"
                 : "+f"(d[0]), "+f"(d[1]), "+f"(d[2]), "+f"(d[3])
                 : "r"(a[0]), "r"(a[1]), "r"(a[2]), "r"(a[3]), "r"(b[0]), "r"(b[1]));
}
__device__ __forceinline__ void cp16(uint32_t saddr, const void* gaddr) {
    asm volatile("cp.async.cg.shared.global [%0], [%1], 16;" :: "r"(saddr), "l"(gaddr));
}

// ---- prep: W (4,64,64) -> w_frag, RN-rounded to tf32, fragment layout ----
// b0: k = lane&3, n = lane>>2 ;  b1: k = (lane&3)+4 (per 8x8 tile)
// 14-bit index: r(1) lane(5) ks(3) nt(1) cw(2) deg(2)
__global__ void prep_kernel(const float* __restrict__ weight) {
    int i = blockIdx.x * blockDim.x + threadIdx.x;   // 0..16383
    int r    = i & 1;
    int lane = (i >> 1) & 31;
    int ks   = (i >> 6) & 7;
    int nt   = (i >> 9) & 1;
    int cw   = (i >> 10) & 3;
    int deg  = (i >> 12) & 3;
    int n = cw * 16 + nt * 8 + (lane >> 2);
    int k = ks * 8 + (lane & 3) + r * 4;
    float v = weight[deg * 4096 + k * 64 + n];
    uint32_t tf;
    asm("cvt.rna.tf32.f32 %0, %1;" : "=r"(tf) : "f"(v));  // round-to-nearest tf32
    w_frag[i] = __uint_as_float(tf);
}

// ---- main: x (65536,25,64) -> out (65536,35,64) ----
// out[n,m,:] = x[n,m+1,:] @ W[deg(m)] ; out[n,24:35,:] = 0
__global__ __launch_bounds__(THREADS, 6)
void dwl_main(const float* __restrict__ x, float* __restrict__ out)
{
    extern __shared__ float xs[];
    const int t    = threadIdx.x;
    const int lane = t & 31;
    const int cw   = t >> 5;                 // col-warp: cols cw*16..cw*16+15
    const long long n0 = (long long)blockIdx.x * NB;

    // zero-fill orders 24..34
    {
        const float4 z = make_float4(0.f, 0.f, 0.f, 0.f);
        for (int i = t; i < NB * 176; i += THREADS) {
            int r = i / 176;
            int j = i - r * 176;
            ((float4*)(out + (n0 + r) * 2240 + 1536))[j] = z;
        }
    }

    const uint32_t xs_b = smem_u32(xs);
    const uint32_t mhi  = 0xFFFFE000u;

    // A-frag ldmatrix addressing (validated R5/R7)
    const uint32_t a_row  = (uint32_t)(lane & 15);
    const uint32_t a_koff = (uint32_t)(lane >> 4) * 16;

    // stage x tile for order m into ring slot b (32 rows x 16 x 16B chunks)
    auto stage = [&](int m, int b) {
        const char* Xg = (const char*)(x + (n0 * 25 + (m + 1)) * 64);
        uint32_t sb = xs_b + b * (BUFF * 4);
        #pragma unroll
        for (int j = 0; j < 4; j++) {
            int i = t + THREADS * j;
            int r = i >> 4;
            int c = i & 15;
            cp16(sb + (uint32_t)(r * (XS * 4) + c * 16),
                 Xg + (long long)r * 6400 + c * 16);
        }
        asm volatile("cp.async.commit_group;" ::: "memory");
    };

    uint32_t bh[2][8][2];
    auto load_bfrags = [&](int deg) {
        #pragma unroll
        for (int nt = 0; nt < 2; nt++)
            #pragma unroll
            for (int ks = 0; ks < 8; ks++) {
                const float* p = w_frag + ((((deg * 4 + cw) * 2 + nt) * 8 + ks)) * 64
                                 + lane * 2;
                float2 h2 = *(const float2*)p;
                bh[nt][ks][0] = __float_as_uint(h2.x);
                bh[nt][ks][1] = __float_as_uint(h2.y);
            }
    };

    stage(0, 0);
    load_bfrags(0);
    int deg = 0;

    for (int m = 0; m < 24; m++) {
        if (m < 23) {
            stage(m + 1, (m + 1) % 3);
            asm volatile("cp.async.wait_group 1;" ::: "memory");
        } else {
            asm volatile("cp.async.wait_group 0;" ::: "memory");
        }
        __syncthreads();

        if (m == 3 || m == 8 || m == 15) { deg++; load_bfrags(deg); }

        const uint32_t abase0 = xs_b + (m % 3) * (BUFF * 4) + a_row * (XS * 4) + a_koff;

        #pragma unroll
        for (int mt = 0; mt < 2; mt++) {
            float acc0[4] = {0.f, 0.f, 0.f, 0.f};
            float acc1[4] = {0.f, 0.f, 0.f, 0.f};
            const uint32_t abase = abase0 + (uint32_t)(mt * 16 * XS * 4);
            #pragma unroll
            for (int ks = 0; ks < 8; ks++) {
                uint32_t a[4];
                ldsm_x4(a, abase + ks * 32);
                uint32_t ah[4], al[4];
                #pragma unroll
                for (int j = 0; j < 4; j++) {
                    ah[j] = a[j] & mhi;                       // exact hi (A split is exact)
                    float lo = __uint_as_float(a[j]) - __uint_as_float(ah[j]);
                    al[j] = __float_as_uint(lo);
                }
                mma_tf32(acc0, ah, bh[0][ks]);
                mma_tf32(acc0, al, bh[0][ks]);
                mma_tf32(acc1, ah, bh[1][ks]);
                mma_tf32(acc1, al, bh[1][ks]);
            }
            const long long row = n0 + mt * 16 + (lane >> 2);
            const int col = m * 64 + cw * 16 + (lane & 3) * 2;
            *(float2*)(out + row * 2240 + col)           = make_float2(acc0[0], acc0[1]);
            *(float2*)(out + (row + 8) * 2240 + col)     = make_float2(acc0[2], acc0[3]);
            *(float2*)(out + row * 2240 + col + 8)       = make_float2(acc1[0], acc1[1]);
            *(float2*)(out + (row + 8) * 2240 + col + 8) = make_float2(acc1[2], acc1[3]);
        }
        // ring depth 3: slot written in iter m was last read in iter m-2;
        // the barrier in iter m-1 orders those reads before these writes.
    }
}

extern "C" void kernel_launch(void* const* d_in, const int* in_sizes, int n_in,
                              void* d_out, int out_size)
{
    const float* x = (const float*)d_in[0];
    const float* w = (const float*)d_in[1];
    if (n_in >= 2 && in_sizes[0] < in_sizes[1]) {
        x = (const float*)d_in[1];
        w = (const float*)d_in[0];
    }
    float* out = (float*)d_out;

    prep_kernel<<<16, 1024>>>(w);   // 16384 threads: one per w_frag element

    const int smem_sz = 3 * BUFF * sizeof(float);   // 26112 B
    cudaFuncSetAttribute(dwl_main, cudaFuncAttributeMaxDynamicSharedMemorySize, smem_sz);
    dwl_main<<<65536 / NB, THREADS, smem_sz>>>(x, out);
}

// round 9
// speedup vs baseline: 2.0627x; 1.0040x over previous
#include <cuda_runtime.h>
#include <cstdint>

#define THREADS 128
#define NB 32
#define XS 68                    // smem row stride (floats): 272B, conflict-free LDSM phases
#define BUFF (NB * XS)           // floats per x ring buffer

// W^T (tf32 RN-rounded) in per-lane mma-fragment order:
// [deg][cw][nt][ks][lane*2+r]  -> 4*4*2*8*64 = 16384 floats
__device__ float w_frag[4 * 4 * 2 * 8 * 64];

__device__ __forceinline__ uint32_t smem_u32(const void* p) {
    uint32_t a;
    asm("{ .reg .u64 t; cvta.to.shared.u64 t, %1; cvt.u32.u64 %0, t; }" : "=r"(a) : "l"(p));
    return a;
}
__device__ __forceinline__ void ldsm_x4(uint32_t* r, uint32_t addr) {
    asm volatile("ldmatrix.sync.aligned.m8n8.x4.shared.b16 {%0,%1,%2,%3}, [%4];"
                 : "=r"(r[0]), "=r"(r[1]), "=r"(r[2]), "=r"(r[3]) : "r"(addr));
}
__device__ __forceinline__ void mma_tf32(float* d, const uint32_t* a, const uint32_t* b) {
    asm volatile("mma.sync.aligned.m16n8k8.row.col.f32.tf32.tf32.f32 "
                 "{%0,%1,%2,%3},{%4,%5,%6,%7},{%8,%9},{%0,%1,%2,%3};"
                 : "+f"(d[0]), "+f"(d[1]), "+f"(d[2]), "+f"(d[3])
                 : "r"(a[0]), "r"(a[1]), "r"(a[2]), "r"(a[3]), "r"(b[0]), "r"(b[1]));
}
__device__ __forceinline__ void cp16(uint32_t saddr, const void* gaddr) {
    asm volatile("cp.async.cg.shared.global [%0], [%1], 16;" :: "r"(saddr), "l"(gaddr));
}
__device__ __forceinline__ uint32_t to_tf32(uint32_t v) {
    uint32_t r;
    asm("cvt.rna.tf32.f32 %0, %1;" : "=r"(r) : "f"(__uint_as_float(v)));
    return r;
}

// ---- prep: W (4,64,64) -> w_frag, RN-rounded to tf32, fragment layout ----
// b0: k = lane&3, n = lane>>2 ;  b1: k = (lane&3)+4 (per 8x8 tile)
// 14-bit index: r(1) lane(5) ks(3) nt(1) cw(2) deg(2)
__global__ void prep_kernel(const float* __restrict__ weight) {
    int i = blockIdx.x * blockDim.x + threadIdx.x;   // 0..16383
    int r    = i & 1;
    int lane = (i >> 1) & 31;
    int ks   = (i >> 6) & 7;
    int nt   = (i >> 9) & 1;
    int cw   = (i >> 10) & 3;
    int deg  = (i >> 12) & 3;
    int n = cw * 16 + nt * 8 + (lane >> 2);
    int k = ks * 8 + (lane & 3) + r * 4;
    float v = weight[deg * 4096 + k * 64 + n];
    uint32_t tf;
    asm("cvt.rna.tf32.f32 %0, %1;" : "=r"(tf) : "f"(v));
    w_frag[i] = __uint_as_float(tf);
}

// ---- main: x (65536,25,64) -> out (65536,35,64) ----
// out[n,m,:] = x[n,m+1,:] @ W[deg(m)] ; out[n,24:35,:] = 0
__global__ __launch_bounds__(THREADS, 7)
void dwl_main(const float* __restrict__ x, float* __restrict__ out)
{
    extern __shared__ float xs[];
    const int t    = threadIdx.x;
    const int lane = t & 31;
    const int cw   = t >> 5;                 // col-warp: cols cw*16..cw*16+15
    const long long n0 = (long long)blockIdx.x * NB;

    // zero-fill orders 24..34
    {
        const float4 z = make_float4(0.f, 0.f, 0.f, 0.f);
        for (int i = t; i < NB * 176; i += THREADS) {
            int r = i / 176;
            int j = i - r * 176;
            ((float4*)(out + (n0 + r) * 2240 + 1536))[j] = z;
        }
    }

    const uint32_t xs_b = smem_u32(xs);

    // A-frag ldmatrix addressing (validated R5/R7/R8)
    const uint32_t a_row  = (uint32_t)(lane & 15);
    const uint32_t a_koff = (uint32_t)(lane >> 4) * 16;

    // stage x tile for order m into ring slot b (32 rows x 16 x 16B chunks)
    auto stage = [&](int m, int b) {
        const char* Xg = (const char*)(x + (n0 * 25 + (m + 1)) * 64);
        uint32_t sb = xs_b + b * (BUFF * 4);
        #pragma unroll
        for (int j = 0; j < 4; j++) {
            int i = t + THREADS * j;
            int r = i >> 4;
            int c = i & 15;
            cp16(sb + (uint32_t)(r * (XS * 4) + c * 16),
                 Xg + (long long)r * 6400 + c * 16);
        }
        asm volatile("cp.async.commit_group;" ::: "memory");
    };

    uint32_t bh[2][8][2];
    auto load_bfrags = [&](int deg) {
        #pragma unroll
        for (int nt = 0; nt < 2; nt++)
            #pragma unroll
            for (int ks = 0; ks < 8; ks++) {
                const float* p = w_frag + ((((deg * 4 + cw) * 2 + nt) * 8 + ks)) * 64
                                 + lane * 2;
                float2 h2 = *(const float2*)p;
                bh[nt][ks][0] = __float_as_uint(h2.x);
                bh[nt][ks][1] = __float_as_uint(h2.y);
            }
    };

    stage(0, 0);
    load_bfrags(0);
    int deg = 0;

    for (int m = 0; m < 24; m++) {
        if (m < 23) {
            stage(m + 1, (m + 1) % 3);
            asm volatile("cp.async.wait_group 1;" ::: "memory");
        } else {
            asm volatile("cp.async.wait_group 0;" ::: "memory");
        }
        __syncthreads();

        if (m == 3 || m == 8 || m == 15) { deg++; load_bfrags(deg); }

        const uint32_t abase0 = xs_b + (m % 3) * (BUFF * 4) + a_row * (XS * 4) + a_koff;

        #pragma unroll
        for (int mt = 0; mt < 2; mt++) {
            float acc0[4] = {0.f, 0.f, 0.f, 0.f};
            float acc1[4] = {0.f, 0.f, 0.f, 0.f};
            const uint32_t abase = abase0 + (uint32_t)(mt * 16 * XS * 4);
            #pragma unroll
            for (int ks = 0; ks < 8; ks++) {
                uint32_t a[4];
                ldsm_x4(a, abase + ks * 32);
                #pragma unroll
                for (int j = 0; j < 4; j++) a[j] = to_tf32(a[j]);  // RN round A
                mma_tf32(acc0, a, bh[0][ks]);
                mma_tf32(acc1, a, bh[1][ks]);
            }
            const long long row = n0 + mt * 16 + (lane >> 2);
            const int col = m * 64 + cw * 16 + (lane & 3) * 2;
            *(float2*)(out + row * 2240 + col)           = make_float2(acc0[0], acc0[1]);
            *(float2*)(out + (row + 8) * 2240 + col)     = make_float2(acc0[2], acc0[3]);
            *(float2*)(out + row * 2240 + col + 8)       = make_float2(acc1[0], acc1[1]);
            *(float2*)(out + (row + 8) * 2240 + col + 8) = make_float2(acc1[2], acc1[3]);
        }
        // ring depth 3: slot written in iter m was last read in iter m-2;
        // the barrier in iter m-1 orders those reads before these writes.
    }
}

extern "C" void kernel_launch(void* const* d_in, const int* in_sizes, int n_in,
                              void* d_out, int out_size)
{
    const float* x = (const float*)d_in[0];
    const float* w = (const float*)d_in[1];
    if (n_in >= 2 && in_sizes[0] < in_sizes[1]) {
        x = (const float*)d_in[1];
        w = (const float*)d_in[0];
    }
    float* out = (float*)d_out;

    prep_kernel<<<16, 1024>>>(w);   // 16384 threads: one per w_frag element

    const int smem_sz = 3 * BUFF * sizeof(float);   // 26112 B
    cudaFuncSetAttribute(dwl_main, cudaFuncAttributeMaxDynamicSharedMemorySize, smem_sz);
    dwl_main<<<65536 / NB, THREADS, smem_sz>>>(x, out);
}

// round 10
// speedup vs baseline: 2.0905x; 1.0135x over previous
#include <cuda_runtime.h>
#include <cstdint>

#define THREADS 128
#define NB 32
#define XS 68                    // smem row stride (floats): 272B, conflict-free LDSM phases
#define BUFF (NB * XS)           // floats per x ring buffer

__device__ __forceinline__ uint32_t smem_u32(const void* p) {
    uint32_t a;
    asm("{ .reg .u64 t; cvta.to.shared.u64 t, %1; cvt.u32.u64 %0, t; }" : "=r"(a) : "l"(p));
    return a;
}
__device__ __forceinline__ void ldsm_x4(uint32_t* r, uint32_t addr) {
    asm volatile("ldmatrix.sync.aligned.m8n8.x4.shared.b16 {%0,%1,%2,%3}, [%4];"
                 : "=r"(r[0]), "=r"(r[1]), "=r"(r[2]), "=r"(r[3]) : "r"(addr));
}
__device__ __forceinline__ void mma_tf32(float* d, const uint32_t* a, const uint32_t* b) {
    asm volatile("mma.sync.aligned.m16n8k8.row.col.f32.tf32.tf32.f32 "
                 "{%0,%1,%2,%3},{%4,%5,%6,%7},{%8,%9},{%0,%1,%2,%3};"
                 : "+f"(d[0]), "+f"(d[1]), "+f"(d[2]), "+f"(d[3])
                 : "r"(a[0]), "r"(a[1]), "r"(a[2]), "r"(a[3]), "r"(b[0]), "r"(b[1]));
}
__device__ __forceinline__ void cp16(uint32_t saddr, const void* gaddr) {
    asm volatile("cp.async.cg.shared.global [%0], [%1], 16;" :: "r"(saddr), "l"(gaddr));
}
__device__ __forceinline__ uint32_t to_tf32(float v) {
    uint32_t r;
    asm("cvt.rna.tf32.f32 %0, %1;" : "=r"(r) : "f"(v));
    return r;
}
__device__ __forceinline__ uint32_t to_tf32u(uint32_t v) {
    uint32_t r;
    asm("cvt.rna.tf32.f32 %0, %1;" : "=r"(r) : "f"(__uint_as_float(v)));
    return r;
}

// ---- single kernel: x (65536,25,64), weight (4,64,64) -> out (65536,35,64) ----
// out[n,m,:] = x[n,m+1,:] @ W[deg(m)] ; out[n,24:35,:] = 0
__global__ __launch_bounds__(THREADS, 7)
void dwl_main(const float* __restrict__ x,
              const float* __restrict__ weight,
              float* __restrict__ out)
{
    extern __shared__ float xs[];
    const int t    = threadIdx.x;
    const int lane = t & 31;
    const int cw   = t >> 5;                 // col-warp: cols cw*16..cw*16+15
    const long long n0 = (long long)blockIdx.x * NB;

    // zero-fill orders 24..34
    {
        const float4 z = make_float4(0.f, 0.f, 0.f, 0.f);
        for (int i = t; i < NB * 176; i += THREADS) {
            int r = i / 176;
            int j = i - r * 176;
            ((float4*)(out + (n0 + r) * 2240 + 1536))[j] = z;
        }
    }

    const uint32_t xs_b = smem_u32(xs);

    // A-frag ldmatrix addressing (validated R5/R7/R8/R9)
    const uint32_t a_row  = (uint32_t)(lane & 15);
    const uint32_t a_koff = (uint32_t)(lane >> 4) * 16;

    // stage x tile for order m into ring slot b (32 rows x 16 x 16B chunks)
    auto stage = [&](int m, int b) {
        const char* Xg = (const char*)(x + (n0 * 25 + (m + 1)) * 64);
        uint32_t sb = xs_b + b * (BUFF * 4);
        #pragma unroll
        for (int j = 0; j < 4; j++) {
            int i = t + THREADS * j;
            int r = i >> 4;
            int c = i & 15;
            cp16(sb + (uint32_t)(r * (XS * 4) + c * 16),
                 Xg + (long long)r * 6400 + c * 16);
        }
        asm volatile("cp.async.commit_group;" ::: "memory");
    };

    // B fragments straight from weight (LDG, L2-hot) + RN tf32 round.
    // Per 8x8 tile: b0 k = lane&3, b1 k = (lane&3)+4; n = lane>>2.
    uint32_t bh[2][8][2];
    const int bn_lo = lane >> 2;             // n offset within 8
    const int bk_lo = lane & 3;              // k offset within 4
    auto load_bfrags = [&](int deg) {
        const float* wb = weight + deg * 4096 + bk_lo * 64 + cw * 16 + bn_lo;
        #pragma unroll
        for (int nt = 0; nt < 2; nt++)
            #pragma unroll
            for (int ks = 0; ks < 8; ks++) {
                const float* p = wb + ks * 512 + nt * 8;
                bh[nt][ks][0] = to_tf32(p[0]);       // k = ks*8 + bk_lo
                bh[nt][ks][1] = to_tf32(p[256]);     // k = ks*8 + bk_lo + 4
            }
    };

    stage(0, 0);
    load_bfrags(0);
    int deg = 0;

    for (int m = 0; m < 24; m++) {
        if (m < 23) {
            stage(m + 1, (m + 1) % 3);
            asm volatile("cp.async.wait_group 1;" ::: "memory");
        } else {
            asm volatile("cp.async.wait_group 0;" ::: "memory");
        }
        __syncthreads();

        if (m == 3 || m == 8 || m == 15) { deg++; load_bfrags(deg); }

        const uint32_t abase0 = xs_b + (m % 3) * (BUFF * 4) + a_row * (XS * 4) + a_koff;

        #pragma unroll
        for (int mt = 0; mt < 2; mt++) {
            float acc0[4] = {0.f, 0.f, 0.f, 0.f};
            float acc1[4] = {0.f, 0.f, 0.f, 0.f};
            const uint32_t abase = abase0 + (uint32_t)(mt * 16 * XS * 4);
            #pragma unroll
            for (int ks = 0; ks < 8; ks++) {
                uint32_t a[4];
                ldsm_x4(a, abase + ks * 32);
                #pragma unroll
                for (int j = 0; j < 4; j++) a[j] = to_tf32u(a[j]);  // RN round A
                mma_tf32(acc0, a, bh[0][ks]);
                mma_tf32(acc1, a, bh[1][ks]);
            }
            const long long row = n0 + mt * 16 + (lane >> 2);
            const int col = m * 64 + cw * 16 + (lane & 3) * 2;
            *(float2*)(out + row * 2240 + col)           = make_float2(acc0[0], acc0[1]);
            *(float2*)(out + (row + 8) * 2240 + col)     = make_float2(acc0[2], acc0[3]);
            *(float2*)(out + row * 2240 + col + 8)       = make_float2(acc1[0], acc1[1]);
            *(float2*)(out + (row + 8) * 2240 + col + 8) = make_float2(acc1[2], acc1[3]);
        }
        // ring depth 3: slot written in iter m was last read in iter m-2;
        // the barrier in iter m-1 orders those reads before these writes.
    }
}

extern "C" void kernel_launch(void* const* d_in, const int* in_sizes, int n_in,
                              void* d_out, int out_size)
{
    const float* x = (const float*)d_in[0];
    const float* w = (const float*)d_in[1];
    if (n_in >= 2 && in_sizes[0] < in_sizes[1]) {
        x = (const float*)d_in[1];
        w = (const float*)d_in[0];
    }
    float* out = (float*)d_out;

    const int smem_sz = 3 * BUFF * sizeof(float);   // 26112 B
    cudaFuncSetAttribute(dwl_main, cudaFuncAttributeMaxDynamicSharedMemorySize, smem_sz);
    dwl_main<<<65536 / NB, THREADS, smem_sz>>>(x, w, out);
}